// round 5
// baseline (speedup 1.0000x reference)
#include <cuda_runtime.h>

// Problem constants (fixed by setup_inputs)
constexpr int B = 4, S = 4096, D = 256, M = 256, H = 8;
constexpr int NC = 32;               // split-K chunks for context GEMM
constexpr int CHUNK = S / NC;        // 128 rows per chunk
constexpr float LNEPS = 1e-5f;
constexpr float KEPS  = 1e-4f;
constexpr float DN    = 0.25f;       // 256^-0.25
constexpr float RATIO = 0.0625f;     // 256^-0.5

// Scratch (device globals; allocation APIs are forbidden)
__device__ float g_xn[B * S * D];          // 16.8 MB  layernormed x (= v)
__device__ float g_diag[B * S];
__device__ float g_pd[B * S * M];          // 16.8 MB  scaled projection
__device__ float g_rowmax[B * S];
__device__ float g_bmax[B];
__device__ float g_pctx[B * NC * M * D];   // 33.5 MB  split-K partials
__device__ float g_pksum[B * NC * M];
__device__ float g_ctx[B * M * D];
__device__ float g_ksum[B * M];

// ---- packed f32x2 helpers (exact fp32, 2x FFMA rate) ----
__device__ __forceinline__ unsigned long long pack2(float lo, float hi) {
    unsigned long long r;
    asm("mov.b64 %0, {%1,%2};" : "=l"(r) : "f"(lo), "f"(hi));
    return r;
}
__device__ __forceinline__ unsigned long long fma2(unsigned long long a,
                                                   unsigned long long b,
                                                   unsigned long long c) {
    unsigned long long d;
    asm("fma.rn.f32x2 %0, %1, %2, %3;" : "=l"(d) : "l"(a), "l"(b), "l"(c));
    return d;
}
__device__ __forceinline__ float2 unpack2(unsigned long long v) {
    float2 f;
    asm("mov.b64 {%0,%1}, %2;" : "=f"(f.x), "=f"(f.y) : "l"(v));
    return f;
}

// ============================================================
// K1: LayerNorm + diag (one block per row, 256 threads = D)
// ============================================================
__global__ void __launch_bounds__(256) k_ln(const float* __restrict__ x,
                                            const float* __restrict__ gamma,
                                            const float* __restrict__ beta) {
    const int row = blockIdx.x;            // b*S + s
    const int t = threadIdx.x;
    const float v = x[(size_t)row * D + t];
    __shared__ float s1[8], s2[8];
    float a = v, b2 = v * v;
#pragma unroll
    for (int o = 16; o; o >>= 1) {
        a  += __shfl_down_sync(~0u, a, o);
        b2 += __shfl_down_sync(~0u, b2, o);
    }
    if ((t & 31) == 0) { s1[t >> 5] = a; s2[t >> 5] = b2; }
    __syncthreads();
    float sum = 0.f, sq = 0.f;
#pragma unroll
    for (int i = 0; i < 8; i++) { sum += s1[i]; sq += s2[i]; }
    const float mu = sum * (1.0f / D);
    const float var = sq * (1.0f / D) - mu * mu;
    const float rstd = rsqrtf(var + LNEPS);
    const float xv = (v - mu) * rstd * gamma[t] + beta[t];
    g_xn[(size_t)row * D + t] = xv;
    // diag = 0.5 * DN^2 * sum(xv^2)
    float c = xv * xv;
#pragma unroll
    for (int o = 16; o; o >>= 1) c += __shfl_down_sync(~0u, c, o);
    __syncthreads();
    if ((t & 31) == 0) s1[t >> 5] = c;
    __syncthreads();
    if (t == 0) {
        float d = 0.f;
#pragma unroll
        for (int i = 0; i < 8; i++) d += s1[i];
        g_diag[row] = d * (0.5f * DN * DN);
    }
}

// ============================================================
// K2: pd[b,s,m] = DN * sum_d xn[b,s,d] * proj[m,d]
// Tiles: BM=64 (s), BN=64 (m), BK=16; 256 threads, 4x4/thread
// ============================================================
__global__ void __launch_bounds__(256) k_pd(const float* __restrict__ proj) {
    const int b  = blockIdx.z;
    const int s0 = blockIdx.x * 64;
    const int m0 = blockIdx.y * 64;
    __shared__ float As[16][68];
    __shared__ float Bs[16][68];
    const int t = threadIdx.x;
    const int tx = t & 15, ty = t >> 4;
    const float* xa = g_xn + ((size_t)b * S + s0) * D;
    const float* pb = proj + (size_t)m0 * D;
    unsigned long long acc[4][2] = {};
    const int lr = t >> 2;            // 0..63 tile row
    const int lc = (t & 3) * 4;       // k offset 0/4/8/12
    for (int k0 = 0; k0 < D; k0 += 16) {
        float4 av = *(const float4*)(xa + (size_t)lr * D + k0 + lc);
        float4 bv = *(const float4*)(pb + (size_t)lr * D + k0 + lc);
        As[lc + 0][lr] = av.x; As[lc + 1][lr] = av.y;
        As[lc + 2][lr] = av.z; As[lc + 3][lr] = av.w;
        Bs[lc + 0][lr] = bv.x; Bs[lc + 1][lr] = bv.y;
        Bs[lc + 2][lr] = bv.z; Bs[lc + 3][lr] = bv.w;
        __syncthreads();
#pragma unroll
        for (int k = 0; k < 16; k++) {
            const unsigned long long b0 = *(const unsigned long long*)&Bs[k][tx * 4];
            const unsigned long long b1 = *(const unsigned long long*)&Bs[k][tx * 4 + 2];
#pragma unroll
            for (int ii = 0; ii < 4; ii++) {
                const float av0 = As[k][ty * 4 + ii];
                const unsigned long long ap = pack2(av0, av0);
                acc[ii][0] = fma2(ap, b0, acc[ii][0]);
                acc[ii][1] = fma2(ap, b1, acc[ii][1]);
            }
        }
        __syncthreads();
    }
#pragma unroll
    for (int ii = 0; ii < 4; ii++) {
        const float2 v0 = unpack2(acc[ii][0]);
        const float2 v1 = unpack2(acc[ii][1]);
        float4 o4 = make_float4(v0.x * DN, v0.y * DN, v1.x * DN, v1.y * DN);
        *(float4*)(g_pd + ((size_t)b * S + s0 + ty * 4 + ii) * M + m0 + tx * 4) = o4;
    }
}

// ============================================================
// K3a: per-row max of pd (one warp per row, 8 rows per block)
// ============================================================
__global__ void __launch_bounds__(256) k_rowmax() {
    const int t = threadIdx.x, w = t >> 5, lane = t & 31;
    const int row = blockIdx.x * 8 + w;
    const float* p = g_pd + (size_t)row * M;
    float mx = -1e30f;
#pragma unroll
    for (int i = 0; i < 8; i++) mx = fmaxf(mx, p[lane + i * 32]);
#pragma unroll
    for (int o = 16; o; o >>= 1) mx = fmaxf(mx, __shfl_xor_sync(~0u, mx, o));
    if (lane == 0) g_rowmax[row] = mx;
}

// K3b: per-batch max over row maxes
__global__ void __launch_bounds__(256) k_bmax() {
    const int b = blockIdx.x, t = threadIdx.x;
    float mx = -1e30f;
    for (int i = t; i < S; i += 256) mx = fmaxf(mx, g_rowmax[b * S + i]);
    __shared__ float sm[8];
#pragma unroll
    for (int o = 16; o; o >>= 1) mx = fmaxf(mx, __shfl_xor_sync(~0u, mx, o));
    if ((t & 31) == 0) sm[t >> 5] = mx;
    __syncthreads();
    if (t == 0) {
        float m2 = sm[0];
#pragma unroll
        for (int i = 1; i < 8; i++) m2 = fmaxf(m2, sm[i]);
        g_bmax[b] = m2;
    }
}

// ============================================================
// K4: split-K context partials.
// pctx[b,c,m,d] = sum_{s in chunk c} k[s,m]*xn[s,d]; pksum[b,c,m]
// grid (M/64, D/64, B*NC); k recomputed from pd via exp.
// ============================================================
__global__ void __launch_bounds__(256) k_ctx() {
    const int b = blockIdx.z / NC, c = blockIdx.z % NC;
    const int m0 = blockIdx.x * 64, d0 = blockIdx.y * 64;
    const int s0 = c * CHUNK;
    const int t = threadIdx.x, tx = t & 15, ty = t >> 4;
    __shared__ float Ks[16][66];
    __shared__ float Vs[16][66];
    __shared__ float ds[16];
    const float bmax = g_bmax[b];
    unsigned long long acc[4][2] = {};
    float ks = 0.f;
    for (int ss = 0; ss < CHUNK; ss += 16) {
        if (t < 16) ds[t] = g_diag[b * S + s0 + ss + t] + bmax;
        __syncthreads();
#pragma unroll
        for (int r = 0; r < 4; r++) {
            const int e = t + r * 256;
            const int si = e >> 6, mj = e & 63;
            const int srow = s0 + ss + si;
            const float pdv = g_pd[((size_t)b * S + srow) * M + m0 + mj];
            Ks[si][mj] = RATIO * (__expf(pdv - ds[si]) + KEPS);
            Vs[si][mj] = g_xn[((size_t)b * S + srow) * D + d0 + mj];
        }
        __syncthreads();
        if (blockIdx.y == 0 && t < 64) {
            float s = 0.f;
#pragma unroll
            for (int i = 0; i < 16; i++) s += Ks[i][t];
            ks += s;
        }
#pragma unroll
        for (int k = 0; k < 16; k++) {
            const unsigned long long b0 = *(const unsigned long long*)&Vs[k][tx * 4];
            const unsigned long long b1 = *(const unsigned long long*)&Vs[k][tx * 4 + 2];
#pragma unroll
            for (int ii = 0; ii < 4; ii++) {
                const float a = Ks[k][ty * 4 + ii];
                const unsigned long long ap = pack2(a, a);
                acc[ii][0] = fma2(ap, b0, acc[ii][0]);
                acc[ii][1] = fma2(ap, b1, acc[ii][1]);
            }
        }
        __syncthreads();
    }
#pragma unroll
    for (int ii = 0; ii < 4; ii++) {
        const float2 v0 = unpack2(acc[ii][0]);
        const float2 v1 = unpack2(acc[ii][1]);
        float4 o4 = make_float4(v0.x, v0.y, v1.x, v1.y);
        *(float4*)(g_pctx + ((size_t)(b * NC + c) * M + m0 + ty * 4 + ii) * D + d0 + tx * 4) = o4;
    }
    if (blockIdx.y == 0 && t < 64)
        g_pksum[(size_t)(b * NC + c) * M + m0 + t] = ks;
}

// K4b: reduce context partials (deterministic, float4-vectorized)
__global__ void __launch_bounds__(256) k_ctxred() {
    const int v = blockIdx.x * 256 + threadIdx.x;    // float4 index
    const int b = v >> 14;                           // 16384 float4 per batch
    const int off = v & 16383;
    const float4* src = (const float4*)g_pctx + ((size_t)b * NC << 14) + off;
    float4 s = make_float4(0.f, 0.f, 0.f, 0.f);
#pragma unroll
    for (int c = 0; c < NC; c++) {
        const float4 p = src[(size_t)c << 14];
        s.x += p.x; s.y += p.y; s.z += p.z; s.w += p.w;
    }
    ((float4*)g_ctx)[v] = s;
}

// K4c: reduce ksum partials
__global__ void __launch_bounds__(256) k_ksumred() {
    const int b = blockIdx.x, t = threadIdx.x;
    float s = 0.f;
#pragma unroll
    for (int c = 0; c < NC; c++) s += g_pksum[(b * NC + c) * M + t];
    g_ksum[b * M + t] = s;
}

// ============================================================
// K5: out[b,h,s,:] = dinv[s] * q[s,:] @ ctx  (broadcast over 8 heads)
// BM=32 rows/block, full 256 cols; 256 threads; 8x4 accum/thread
// ============================================================
__global__ void __launch_bounds__(256) k_out(float* __restrict__ out) {
    const int b = blockIdx.y, s0 = blockIdx.x * 32;
    const int t = threadIdx.x;
    __shared__ float qs[32][M];     // 32 KB
    __shared__ float Cs[8][D];      // 8 KB
    __shared__ float red[32][8];
    __shared__ float dinv_s[32];
    const int w = t >> 5, lane = t & 31;
    const float ksv = g_ksum[b * M + t];
    // build q tile (row i, col t) + per-row dot(q, ksum) partials
#pragma unroll 4
    for (int i = 0; i < 32; i++) {
        const int srow = s0 + i;
        const float pdv = g_pd[((size_t)b * S + srow) * M + t];
        const float qv = RATIO *
            (__expf(pdv - g_diag[b * S + srow] - g_rowmax[b * S + srow]) + KEPS);
        qs[i][t] = qv;
        float dp = qv * ksv;
#pragma unroll
        for (int o = 16; o; o >>= 1) dp += __shfl_down_sync(~0u, dp, o);
        if (lane == 0) red[i][w] = dp;
    }
    __syncthreads();
    if (t < 32) {
        float s = 0.f;
#pragma unroll
        for (int j = 0; j < 8; j++) s += red[t][j];
        dinv_s[t] = 1.0f / s;
    }
    // GEMM: out_tile[32][256] = qs[32][256] @ ctx[256][256]
    const int tx = t & 63, ty = t >> 6;
    const int c0 = tx * 4, r0 = ty * 8;
    unsigned long long acc[8][2] = {};
    for (int k0 = 0; k0 < M; k0 += 8) {
        __syncthreads();
#pragma unroll
        for (int i = 0; i < 8; i++)
            Cs[i][t] = g_ctx[((size_t)b * M + k0 + i) * D + t];
        __syncthreads();
#pragma unroll
        for (int k = 0; k < 8; k++) {
            const unsigned long long b0 = *(const unsigned long long*)&Cs[k][c0];
            const unsigned long long b1 = *(const unsigned long long*)&Cs[k][c0 + 2];
#pragma unroll
            for (int ii = 0; ii < 8; ii++) {
                const float a = qs[r0 + ii][k0 + k];
                const unsigned long long ap = pack2(a, a);
                acc[ii][0] = fma2(ap, b0, acc[ii][0]);
                acc[ii][1] = fma2(ap, b1, acc[ii][1]);
            }
        }
    }
#pragma unroll
    for (int ii = 0; ii < 8; ii++) {
        const int srow = s0 + r0 + ii;
        const float dinv = dinv_s[r0 + ii];
        const float2 v0 = unpack2(acc[ii][0]);
        const float2 v1 = unpack2(acc[ii][1]);
        float4 o4 = make_float4(v0.x * dinv, v0.y * dinv, v1.x * dinv, v1.y * dinv);
        size_t base = ((size_t)b * H * S + srow) * D + c0;   // h = 0
#pragma unroll
        for (int h = 0; h < H; h++)
            *(float4*)(out + base + (size_t)h * S * D) = o4;
    }
}

extern "C" void kernel_launch(void* const* d_in, const int* in_sizes, int n_in,
                              void* d_out, int out_size) {
    const float* x     = (const float*)d_in[0];
    const float* gamma = (const float*)d_in[1];
    const float* beta  = (const float*)d_in[2];
    const float* proj  = (const float*)d_in[3];
    float* out = (float*)d_out;
    (void)in_sizes; (void)n_in; (void)out_size;

    k_ln<<<B * S, 256>>>(x, gamma, beta);
    k_pd<<<dim3(S / 64, M / 64, B), 256>>>(proj);
    k_rowmax<<<B * S / 8, 256>>>();
    k_bmax<<<B, 256>>>();
    k_ctx<<<dim3(M / 64, D / 64, B * NC), 256>>>();
    k_ctxred<<<B * M * D / 1024, 256>>>();
    k_ksumred<<<B, 256>>>();
    k_out<<<dim3(S / 32, B), 256>>>(out);
}